// round 15
// baseline (speedup 1.0000x reference)
#include <cuda_runtime.h>
#include <cuda_fp16.h>
#include <math_constants.h>
#include <cstdint>

#define N_USERS   100000
#define M_ITEMS   50000
#define N_NODES   (N_USERS + M_ITEMS)
#define LATENT    64
#define N_CATS    1000
#define TIME_BINS 24
#define NNZ       4800000
#define BATCH     1024
#define ALPHA     0.5f
#define M_PAD     50048          // 391 * 128

#define NODEF (N_NODES * LATENT)   // 9.6M elements
#define SCAN_CHUNK 1024
#define NBLK ((N_NODES + SCAN_CHUNK - 1) / SCAN_CHUNK)   // 147
#define NBUCKET 128

typedef unsigned long long ull;

// ---------------- device scratch (static: no allocs allowed) ----------------
__device__ __align__(16) __half g_h0[NODEF];
__device__ __align__(16) __half g_h1[NODEF];
__device__ float g_acc[NODEF];
__device__ float g_Vc[BATCH * 64];
__device__ float g_CT[N_CATS * BATCH];   // CT[cat][b], 4.1 MB
__device__ int2  g_edge[NNZ];            // compact CSR edges (38.4 MB, L2-resident)
__device__ int   g_cnt[N_NODES];
__device__ int   g_rowstart[N_NODES];
__device__ int   g_cursor[N_NODES];
__device__ int   g_blocksums[NBLK];
__device__ int   g_hist[NBUCKET];
__device__ int   g_hcur[NBUCKET];
__device__ int   g_perm[N_NODES];        // rows sorted by degree bucket
__device__ unsigned char g_need[N_USERS];

// ---------------- f32x2 helpers ----------------
__device__ __forceinline__ ull dup2(float x) {
    ull p;
    asm("mov.b64 %0, {%1, %1};" : "=l"(p) : "f"(x));
    return p;
}
__device__ __forceinline__ void fma2(ull& c, ull a, ull b) {
    asm("fma.rn.f32x2 %0, %1, %2, %0;" : "+l"(c) : "l"(a), "l"(b));
}
__device__ __forceinline__ float2 unpack2(ull p) {
    float2 v;
    asm("mov.b64 {%0, %1}, %2;" : "=f"(v.x), "=f"(v.y) : "l"(p));
    return v;
}

// ---------------- init: h0 = fp16(concat(emb)); zero cnt/need/hist ----------------
__global__ void k_init(const float* __restrict__ ue, const float* __restrict__ ie,
                       __half* __restrict__ h0,
                       int* __restrict__ cnt, unsigned char* __restrict__ need,
                       int* __restrict__ hist) {
    int i = blockIdx.x * blockDim.x + threadIdx.x;       // float4 index
    const int total = N_NODES * (LATENT / 4);
    const int usplit = N_USERS * (LATENT / 4);
    if (i < total) {
        float4 v = (i < usplit) ? ((const float4*)ue)[i]
                                : ((const float4*)ie)[i - usplit];
        ((half2*)h0)[i * 2]     = __floats2half2_rn(v.x, v.y);
        ((half2*)h0)[i * 2 + 1] = __floats2half2_rn(v.z, v.w);
    }
    if (i < N_NODES) cnt[i] = 0;
    if (i < N_USERS) need[i] = 0;
    if (i < NBUCKET) hist[i] = 0;
}

// ---------------- CSR build: count (4 edges/thread) ----------------
__global__ void k_count(const int* __restrict__ rows, int* __restrict__ cnt) {
    int e4 = blockIdx.x * blockDim.x + threadIdx.x;
    if (e4 < NNZ / 4) {
        int4 r = ((const int4*)rows)[e4];
        atomicAdd(&cnt[r.x], 1);
        atomicAdd(&cnt[r.y], 1);
        atomicAdd(&cnt[r.z], 1);
        atomicAdd(&cnt[r.w], 1);
    }
}

__global__ __launch_bounds__(256) void k_scan_blocks(const int* __restrict__ cnt,
                                                     int* __restrict__ rowstart,
                                                     int* __restrict__ blocksums) {
    __shared__ int wsum[8];
    __shared__ int woff[8];
    int tid  = threadIdx.x;
    int lane = tid & 31;
    int warp = tid >> 5;
    int base = blockIdx.x * SCAN_CHUNK + tid * 4;

    int c0 = 0, c1 = 0, c2 = 0, c3 = 0;
    if (base + 3 < N_NODES) {
        int4 c = *(const int4*)(cnt + base);
        c0 = c.x; c1 = c.y; c2 = c.z; c3 = c.w;
    } else {
        if (base + 0 < N_NODES) c0 = cnt[base + 0];
        if (base + 1 < N_NODES) c1 = cnt[base + 1];
        if (base + 2 < N_NODES) c2 = cnt[base + 2];
        if (base + 3 < N_NODES) c3 = cnt[base + 3];
    }
    int tsum = c0 + c1 + c2 + c3;

    int inc = tsum;
    #pragma unroll
    for (int off = 1; off < 32; off <<= 1) {
        int n = __shfl_up_sync(0xffffffffu, inc, off);
        if (lane >= off) inc += n;
    }
    if (lane == 31) wsum[warp] = inc;
    __syncthreads();
    if (tid == 0) {
        int r = 0;
        #pragma unroll
        for (int i = 0; i < 8; i++) { woff[i] = r; r += wsum[i]; }
        blocksums[blockIdx.x] = r;           // raw chunk sum
    }
    __syncthreads();

    int excl = woff[warp] + (inc - tsum);
    if (base + 0 < N_NODES) rowstart[base + 0] = excl;
    if (base + 1 < N_NODES) rowstart[base + 1] = excl + c0;
    if (base + 2 < N_NODES) rowstart[base + 2] = excl + c0 + c1;
    if (base + 3 < N_NODES) rowstart[base + 3] = excl + c0 + c1 + c2;
}

// add chunk-prefix + init cursor + degree histogram (smem sub-hist per block)
__global__ __launch_bounds__(256) void k_add_offsets(int* __restrict__ rowstart,
                                                     const int* __restrict__ blocksums,
                                                     int* __restrict__ cursor,
                                                     const int* __restrict__ cnt,
                                                     int* __restrict__ hist) {
    __shared__ int s_off;
    __shared__ int sh[NBUCKET];
    if (threadIdx.x < NBUCKET) sh[threadIdx.x] = 0;
    int chunk = blockIdx.x >> 2;             // 4 blocks of 256 per 1024-chunk
    if (threadIdx.x < 32) {
        int v = 0;
        for (int j = threadIdx.x; j < chunk; j += 32) v += blocksums[j];
        #pragma unroll
        for (int o = 16; o; o >>= 1) v += __shfl_down_sync(0xffffffffu, v, o);
        if (threadIdx.x == 0) s_off = v;
    }
    __syncthreads();
    int i = blockIdx.x * 256 + threadIdx.x;
    if (i < N_NODES) {
        int r = rowstart[i] + s_off;
        rowstart[i] = r;
        cursor[i]   = r;
        int d = cnt[i]; if (d > NBUCKET - 1) d = NBUCKET - 1;
        atomicAdd(&sh[d], 1);
    }
    __syncthreads();
    if (threadIdx.x < NBUCKET && sh[threadIdx.x] > 0)
        atomicAdd(&hist[threadIdx.x], sh[threadIdx.x]);
}

// exclusive scan of 128-bucket hist -> hcur (single warp)
__global__ void k_histscan(const int* __restrict__ hist, int* __restrict__ hcur) {
    if (threadIdx.x == 0 && blockIdx.x == 0) {
        int r = 0;
        for (int i = 0; i < NBUCKET; i++) { int v = hist[i]; hcur[i] = r; r += v; }
    }
}

// scatter rows into degree-sorted permutation
__global__ void k_perm(const int* __restrict__ cnt, int* __restrict__ hcur,
                       int* __restrict__ perm) {
    int i = blockIdx.x * blockDim.x + threadIdx.x;
    if (i < N_NODES) {
        int d = cnt[i]; if (d > NBUCKET - 1) d = NBUCKET - 1;
        int pos = atomicAdd(&hcur[d], 1);
        perm[pos] = i;
    }
}

// ---------------- CSR build: fill (4 edges/thread) ----------------
__global__ void k_fill(const float* __restrict__ vals,
                       const int*   __restrict__ rows,
                       const int*   __restrict__ cols,
                       int* __restrict__ cursor,
                       int2* __restrict__ edge) {
    int e4 = blockIdx.x * blockDim.x + threadIdx.x;
    if (e4 < NNZ / 4) {
        int4   r = ((const int4*)rows)[e4];
        int4   c = ((const int4*)cols)[e4];
        float4 v = ((const float4*)vals)[e4];
        int p;
        p = atomicAdd(&cursor[r.x], 1); edge[p] = make_int2(__float_as_int(v.x), c.x);
        p = atomicAdd(&cursor[r.y], 1); edge[p] = make_int2(__float_as_int(v.y), c.y);
        p = atomicAdd(&cursor[r.z], 1); edge[p] = make_int2(__float_as_int(v.z), c.z);
        p = atomicAdd(&cursor[r.w], 1); edge[p] = make_int2(__float_as_int(v.w), c.w);
    }
}

__global__ void k_setflags(const int* __restrict__ users, unsigned char* __restrict__ need) {
    int i = blockIdx.x * blockDim.x + threadIdx.x;
    if (i < BATCH) need[users[i]] = 1;
}

// ---------------- layer: fp16 segment gather (degree-sorted rows) ----------------
__global__ __launch_bounds__(256) void k_gather(const int2* __restrict__ edge,
                                                const int*  __restrict__ rowstart,
                                                const int*  __restrict__ cnt,
                                                const int*  __restrict__ perm,
                                                const __half* __restrict__ esrc,
                                                __half*       __restrict__ edst,
                                                float*        __restrict__ acc,
                                                const unsigned char* __restrict__ need,
                                                const float* __restrict__ ue,
                                                const float* __restrict__ ie,
                                                int mode) {
    int g   = blockIdx.x * blockDim.x + threadIdx.x;
    int ri  = g >> 3;
    int t   = g & 7;
    if (ri >= N_NODES) return;
    int row = perm[ri];
    if (mode == 2 && row < N_USERS && !need[row]) return;
    unsigned gmask = 0xFFu << (threadIdx.x & 24);   // own 8-lane group

    const int start = rowstart[row];
    const int deg   = cnt[row];
    float s0 = 0.f, s1 = 0.f, s2 = 0.f, s3 = 0.f;
    float s4 = 0.f, s5 = 0.f, s6 = 0.f, s7 = 0.f;

    const int2* ep = edge + start;
    const __half* srcbase = esrc + t * 8;
    int base = 0;
    const int full = deg & ~7;

    for (; base < full; base += 8) {
        int2 ev = __ldg(&ep[base + t]);
        float v[8]; int c[8];
        #pragma unroll
        for (int k = 0; k < 8; k++) {
            v[k] = __int_as_float(__shfl_sync(gmask, ev.x, k, 8));
            c[k] = __shfl_sync(gmask, ev.y, k, 8);
        }
        uint4 m[8];
        #pragma unroll
        for (int k = 0; k < 8; k++)
            m[k] = __ldg((const uint4*)(srcbase + (size_t)c[k] * LATENT));
        #pragma unroll
        for (int k = 0; k < 8; k++) {
            float2 f0 = __half22float2(*(half2*)&m[k].x);
            float2 f1 = __half22float2(*(half2*)&m[k].y);
            float2 f2 = __half22float2(*(half2*)&m[k].z);
            float2 f3 = __half22float2(*(half2*)&m[k].w);
            s0 += v[k] * f0.x; s1 += v[k] * f0.y;
            s2 += v[k] * f1.x; s3 += v[k] * f1.y;
            s4 += v[k] * f2.x; s5 += v[k] * f2.y;
            s6 += v[k] * f3.x; s7 += v[k] * f3.y;
        }
    }
    if (base < deg) {
        int rem = deg - base;
        int2 ev = (t < rem) ? __ldg(&ep[base + t]) : make_int2(0, 0);
        for (int k = 0; k < rem; k++) {
            float v = __int_as_float(__shfl_sync(gmask, ev.x, k, 8));
            int   c = __shfl_sync(gmask, ev.y, k, 8);
            uint4 m = __ldg((const uint4*)(srcbase + (size_t)c * LATENT));
            float2 f0 = __half22float2(*(half2*)&m.x);
            float2 f1 = __half22float2(*(half2*)&m.y);
            float2 f2 = __half22float2(*(half2*)&m.z);
            float2 f3 = __half22float2(*(half2*)&m.w);
            s0 += v * f0.x; s1 += v * f0.y;
            s2 += v * f1.x; s3 += v * f1.y;
            s4 += v * f2.x; s5 += v * f2.y;
            s6 += v * f3.x; s7 += v * f3.y;
        }
    }

    size_t idx = (size_t)row * LATENT + t * 8;
    float4 a0, a1;
    if (mode == 1) {
        const float* emb = (row < N_USERS) ? (ue + (size_t)row * LATENT)
                                           : (ie + (size_t)(row - N_USERS) * LATENT);
        a0 = *(const float4*)(emb + t * 8);
        a1 = *(const float4*)(emb + t * 8 + 4);
    } else {
        a0 = *(float4*)(acc + idx);
        a1 = *(float4*)(acc + idx + 4);
    }
    a0.x += s0; a0.y += s1; a0.z += s2; a0.w += s3;
    a1.x += s4; a1.y += s5; a1.z += s6; a1.w += s7;
    *(float4*)(acc + idx)     = a0;
    *(float4*)(acc + idx + 4) = a1;
    if (mode != 2) {
        uint4 o;
        *(half2*)&o.x = __floats2half2_rn(s0, s1);
        *(half2*)&o.y = __floats2half2_rn(s2, s3);
        *(half2*)&o.z = __floats2half2_rn(s4, s5);
        *(half2*)&o.w = __floats2half2_rn(s6, s7);
        *(uint4*)(edst + idx) = o;
    }
}

// ---------------- v_clock: Vc[b][64] ----------------
__global__ void k_vclock(const float* __restrict__ cat_emb,
                         const int*   __restrict__ uh3,
                         const int*   __restrict__ users,
                         const float* __restrict__ thetas,
                         float*       __restrict__ Vc) {
    int b = blockIdx.x;
    int d = threadIdx.x;       // 64 threads
    __shared__ float w[TIME_BINS];
    __shared__ float sinv;
    int u = users[b];
    if (d < TIME_BINS) {
        float cur = thetas[b] * (float)(TIME_BINS / (2.0 * CUDART_PI));
        float diff = fabsf(cur - (float)d);
        float delta = fminf(diff, (float)TIME_BINS - diff);
        w[d] = __expf(-0.5f * delta * delta);
    }
    __syncthreads();
    if (d == 0) {
        float s = 0.f;
        #pragma unroll
        for (int h = 0; h < TIME_BINS; h++) s += w[h];
        sinv = 1.0f / (s + 1e-8f);
    }
    __syncthreads();
    float inv3 = sinv * (1.0f / 3.0f);
    float v = 0.f;
    const int* base = &uh3[u * TIME_BINS * 3];
    #pragma unroll 4
    for (int h = 0; h < TIME_BINS; h++) {
        int c0 = base[h * 3 + 0], c1 = base[h * 3 + 1], c2 = base[h * 3 + 2];
        float e = cat_emb[c0 * 64 + d] + cat_emb[c1 * 64 + d] + cat_emb[c2 * 64 + d];
        v += w[h] * e;
    }
    Vc[b * 64 + d] = v * inv3;
}

// ---------------- clock table: CT[cat][b] = ALPHA * cat_emb[cat] . Vc[b] ----------------
#define CT_CATS 8
__global__ __launch_bounds__(256) void k_ct(const float* __restrict__ cat_emb,
                                            const float* __restrict__ Vc,
                                            float* __restrict__ CT) {
    __shared__ float sc[CT_CATS][64];
    int cat0 = blockIdx.y * CT_CATS;
    for (int i = threadIdx.x; i < CT_CATS * 64; i += 256) {
        int cc = cat0 + i / 64;
        sc[i / 64][i % 64] = (cc < N_CATS) ? cat_emb[cc * 64 + (i % 64)] : 0.f;
    }
    __syncthreads();
    int b = blockIdx.x * 256 + threadIdx.x;
    float acc[CT_CATS];
    #pragma unroll
    for (int c = 0; c < CT_CATS; c++) acc[c] = 0.f;
    #pragma unroll 4
    for (int k = 0; k < 64; k += 4) {
        float4 v = *(const float4*)(Vc + b * 64 + k);
        #pragma unroll
        for (int c = 0; c < CT_CATS; c++)
            acc[c] += v.x * sc[c][k] + v.y * sc[c][k + 1] + v.z * sc[c][k + 2] + v.w * sc[c][k + 3];
    }
    #pragma unroll
    for (int c = 0; c < CT_CATS; c++)
        if (cat0 + c < N_CATS) CT[(cat0 + c) * BATCH + b] = ALPHA * acc[c];
}

// ---------------- GEMM K=64, BK=16 + smem-staged CT epilogue ----------------
#define BM 128
#define BN 128
#define BK 16
#define TM 8
#define TN 8
#define CT_PAD 132   // multiple of 4 -> float4-aligned staging; epilogue reads broadcast
#define SM_AS 0
#define SM_BS 8192
#define SM_CT 16384
#define SM_GEMM_TOTAL (SM_CT + 128 * CT_PAD * 4)

__global__ __launch_bounds__(256, 2) void k_gemm(const float* __restrict__ acc,
                                                 const int*   __restrict__ users,
                                                 const int*   __restrict__ item_cat,
                                                 const float* __restrict__ CT,
                                                 float* __restrict__ C) {
    extern __shared__ __align__(16) char smem_raw[];
    float (*As)[BM] = (float(*)[BM])(smem_raw + SM_AS);
    float (*Bs)[BN] = (float(*)[BN])(smem_raw + SM_BS);
    float* sct = (float*)(smem_raw + SM_CT);

    const int tid  = threadIdx.x;
    const int row0 = blockIdx.y * BM;   // batch offset
    const int col0 = blockIdx.x * BN;   // item offset
    const int ty   = tid / 16;
    const int tx   = tid % 16;

    ull facc[TM][TN / 2];
    #pragma unroll
    for (int i = 0; i < TM; i++)
        #pragma unroll
        for (int j = 0; j < TN / 2; j++) facc[i][j] = 0ull;

    const int lr = tid >> 1;          // 0..127
    const int lq = (tid & 1) * 8;     // 0 or 8 (8-float segment within BK=16)

    const int u = users[row0 + lr];
    const float* aptr = acc + (size_t)u * LATENT;
    const int bcol = col0 + lr;
    const bool bvalid = bcol < M_ITEMS;
    const float* bptr = acc + (size_t)(N_USERS + bcol) * LATENT;

    // prefetch k0 = 0
    float4 pa0 = *(const float4*)(aptr + lq);
    float4 pa1 = *(const float4*)(aptr + lq + 4);
    float4 pb0 = bvalid ? *(const float4*)(bptr + lq)     : make_float4(0.f, 0.f, 0.f, 0.f);
    float4 pb1 = bvalid ? *(const float4*)(bptr + lq + 4) : make_float4(0.f, 0.f, 0.f, 0.f);

    #pragma unroll
    for (int k0 = 0; k0 < LATENT; k0 += BK) {
        As[lq + 0][lr] = pa0.x; As[lq + 1][lr] = pa0.y; As[lq + 2][lr] = pa0.z; As[lq + 3][lr] = pa0.w;
        As[lq + 4][lr] = pa1.x; As[lq + 5][lr] = pa1.y; As[lq + 6][lr] = pa1.z; As[lq + 7][lr] = pa1.w;
        Bs[lq + 0][lr] = pb0.x; Bs[lq + 1][lr] = pb0.y; Bs[lq + 2][lr] = pb0.z; Bs[lq + 3][lr] = pb0.w;
        Bs[lq + 4][lr] = pb1.x; Bs[lq + 5][lr] = pb1.y; Bs[lq + 6][lr] = pb1.z; Bs[lq + 7][lr] = pb1.w;
        __syncthreads();

        if (k0 + BK < LATENT) {
            int kn = k0 + BK + lq;
            pa0 = *(const float4*)(aptr + kn);
            pa1 = *(const float4*)(aptr + kn + 4);
            pb0 = bvalid ? *(const float4*)(bptr + kn)     : make_float4(0.f, 0.f, 0.f, 0.f);
            pb1 = bvalid ? *(const float4*)(bptr + kn + 4) : make_float4(0.f, 0.f, 0.f, 0.f);
        }

        #pragma unroll
        for (int kk = 0; kk < BK; kk++) {
            float4 a0 = *(const float4*)&As[kk][ty * TM];
            float4 a1 = *(const float4*)&As[kk][ty * TM + 4];
            ulonglong2 bp0 = *(const ulonglong2*)&Bs[kk][tx * TN];
            ulonglong2 bp1 = *(const ulonglong2*)&Bs[kk][tx * TN + 4];
            ull ap[TM];
            ap[0] = dup2(a0.x); ap[1] = dup2(a0.y); ap[2] = dup2(a0.z); ap[3] = dup2(a0.w);
            ap[4] = dup2(a1.x); ap[5] = dup2(a1.y); ap[6] = dup2(a1.z); ap[7] = dup2(a1.w);
            #pragma unroll
            for (int i = 0; i < TM; i++) {
                fma2(facc[i][0], ap[i], bp0.x);
                fma2(facc[i][1], ap[i], bp0.y);
                fma2(facc[i][2], ap[i], bp1.x);
                fma2(facc[i][3], ap[i], bp1.y);
            }
        }
        __syncthreads();
    }

    // ---- stage CT into smem: warp w covers columns 16w..16w+15, coalesced rows ----
    {
        const int w    = tid >> 5;
        const int lane = tid & 31;
        #pragma unroll
        for (int cc = 0; cc < 16; cc += 4) {
            int cat4[4];
            #pragma unroll
            for (int q = 0; q < 4; q++) {
                int col = col0 + w * 16 + cc + q;
                cat4[q] = (col < M_ITEMS) ? __ldg(&item_cat[col]) : 0;
            }
            float4 v4[4];
            #pragma unroll
            for (int q = 0; q < 4; q++)
                v4[q] = __ldg((const float4*)(CT + (size_t)cat4[q] * BATCH + row0 + lane * 4));
            #pragma unroll
            for (int q = 0; q < 4; q++)
                *(float4*)(sct + (w * 16 + cc + q) * CT_PAD + lane * 4) = v4[q];
        }
    }
    __syncthreads();

    // ---- epilogue: scale + smem CT + store ----
    const float scale = 0.0625f;     // 0.25 (user layer-mean) * 0.25 (item layer-mean)
    #pragma unroll
    for (int i = 0; i < TM; i++) {
        int r_loc = ty * TM + i;
        int r = row0 + r_loc;            // always < 1024
        float ct[TN];
        #pragma unroll
        for (int j = 0; j < TN; j++)
            ct[j] = sct[(tx * TN + j) * CT_PAD + r_loc];
        #pragma unroll
        for (int j = 0; j < TN / 2; j += 2) {
            int c = col0 + tx * TN + j * 2;
            if (c < M_ITEMS) {
                float2 v0 = unpack2(facc[i][j]);
                float2 v1 = unpack2(facc[i][j + 1]);
                float4 o = make_float4(scale * v0.x + ct[j * 2 + 0],
                                       scale * v0.y + ct[j * 2 + 1],
                                       scale * v1.x + ct[j * 2 + 2],
                                       scale * v1.y + ct[j * 2 + 3]);
                *(float4*)(C + (size_t)r * M_ITEMS + c) = o;
            }
        }
    }
}

// ---------------- launch ----------------
extern "C" void kernel_launch(void* const* d_in, const int* in_sizes, int n_in,
                              void* d_out, int out_size) {
    const float* user_emb  = (const float*)d_in[0];
    const float* item_emb  = (const float*)d_in[1];
    const float* cat_emb   = (const float*)d_in[2];
    const float* graph_vals= (const float*)d_in[3];
    const int*   graph_rows= (const int*)  d_in[4];
    const int*   graph_cols= (const int*)  d_in[5];
    const int*   uh3       = (const int*)  d_in[6];
    const int*   item_cat  = (const int*)  d_in[7];
    const int*   users     = (const int*)  d_in[8];
    const float* thetas    = (const float*)d_in[9];
    float* out = (float*)d_out;

    __half *d_h0, *d_h1;
    float *d_acc, *d_Vc, *d_CT;
    int2* d_edge; int *d_cnt, *d_rowstart, *d_cursor, *d_blocksums;
    int *d_hist, *d_hcur, *d_perm;
    unsigned char* d_need;
    cudaGetSymbolAddress((void**)&d_h0,       g_h0);
    cudaGetSymbolAddress((void**)&d_h1,       g_h1);
    cudaGetSymbolAddress((void**)&d_acc,      g_acc);
    cudaGetSymbolAddress((void**)&d_Vc,       g_Vc);
    cudaGetSymbolAddress((void**)&d_CT,       g_CT);
    cudaGetSymbolAddress((void**)&d_edge,     g_edge);
    cudaGetSymbolAddress((void**)&d_cnt,      g_cnt);
    cudaGetSymbolAddress((void**)&d_rowstart, g_rowstart);
    cudaGetSymbolAddress((void**)&d_cursor,   g_cursor);
    cudaGetSymbolAddress((void**)&d_blocksums,g_blocksums);
    cudaGetSymbolAddress((void**)&d_hist,     g_hist);
    cudaGetSymbolAddress((void**)&d_hcur,     g_hcur);
    cudaGetSymbolAddress((void**)&d_perm,     g_perm);
    cudaGetSymbolAddress((void**)&d_need,     g_need);

    cudaFuncSetAttribute(k_gemm, cudaFuncAttributeMaxDynamicSharedMemorySize, SM_GEMM_TOTAL);

    // 1: init (h0 + zero cnt/need/hist)
    {
        int total = N_NODES * (LATENT / 4);
        k_init<<<(total + 255) / 256, 256>>>(user_emb, item_emb, d_h0, d_cnt, d_need, d_hist);
    }
    // 2-7: CSR build + degree-sorted permutation
    k_count<<<(NNZ / 4 + 255) / 256, 256>>>(graph_rows, d_cnt);
    k_scan_blocks<<<NBLK, 256>>>(d_cnt, d_rowstart, d_blocksums);
    k_add_offsets<<<NBLK * 4, 256>>>(d_rowstart, d_blocksums, d_cursor, d_cnt, d_hist);
    k_histscan<<<1, 32>>>(d_hist, d_hcur);
    k_perm<<<(N_NODES + 255) / 256, 256>>>(d_cnt, d_hcur, d_perm);
    k_fill<<<(NNZ / 4 + 255) / 256, 256>>>(graph_vals, graph_rows, graph_cols, d_cursor, d_edge);

    // 8-11: LightGCN layers
    {
        int th = N_NODES * 8;
        int blocks = (th + 255) / 256;
        k_gather<<<blocks, 256>>>(d_edge, d_rowstart, d_cnt, d_perm, d_h0, d_h1, d_acc, d_need,
                                  user_emb, item_emb, 1);   // L1: acc = emb + s
        k_gather<<<blocks, 256>>>(d_edge, d_rowstart, d_cnt, d_perm, d_h1, d_h0, d_acc, d_need,
                                  user_emb, item_emb, 0);   // L2: acc += s
        k_setflags<<<(BATCH + 255) / 256, 256>>>(users, d_need);
        k_gather<<<blocks, 256>>>(d_edge, d_rowstart, d_cnt, d_perm, d_h0, d_h1, d_acc, d_need,
                                  user_emb, item_emb, 2);   // L3: selective
    }

    // 12-13: clock path
    k_vclock<<<BATCH, 64>>>(cat_emb, uh3, users, thetas, d_Vc);
    {
        dim3 grid(BATCH / 256, (N_CATS + CT_CATS - 1) / CT_CATS);
        k_ct<<<grid, 256>>>(cat_emb, d_Vc, d_CT);
    }

    // 14: fused GEMM (K=64) + staged-CT epilogue
    {
        dim3 grid(M_PAD / BN, BATCH / BM);
        k_gemm<<<grid, 256, SM_GEMM_TOTAL>>>(d_acc, users, item_cat, d_CT, out);
    }
}

// round 16
// speedup vs baseline: 1.1119x; 1.1119x over previous
#include <cuda_runtime.h>
#include <cuda_fp16.h>
#include <math_constants.h>
#include <cstdint>

#define N_USERS   100000
#define M_ITEMS   50000
#define N_NODES   (N_USERS + M_ITEMS)
#define LATENT    64
#define N_CATS    1000
#define TIME_BINS 24
#define NNZ       4800000
#define BATCH     1024
#define ALPHA     0.5f
#define M_PAD     50048          // 391 * 128

#define NODEF (N_NODES * LATENT)   // 9.6M elements
#define SCAN_CHUNK 1024
#define NBLK ((N_NODES + SCAN_CHUNK - 1) / SCAN_CHUNK)   // 147

typedef unsigned long long ull;

// ---------------- device scratch (static: no allocs allowed) ----------------
__device__ __align__(16) __half g_h0[NODEF];
__device__ __align__(16) __half g_h1[NODEF];
__device__ float g_acc[NODEF];
__device__ float g_Vc[BATCH * 64];
__device__ float g_CT[N_CATS * BATCH];   // CT[cat][b], 4.1 MB
__device__ int2  g_edge[NNZ];            // compact CSR edges (38.4 MB, L2-resident)
__device__ int   g_cnt[N_NODES];
__device__ int   g_rowstart[N_NODES];
__device__ int   g_cursor[N_NODES];
__device__ int   g_blocksums[NBLK];
__device__ unsigned char g_need[N_USERS];

// ---------------- f32x2 helpers ----------------
__device__ __forceinline__ ull dup2(float x) {
    ull p;
    asm("mov.b64 %0, {%1, %1};" : "=l"(p) : "f"(x));
    return p;
}
__device__ __forceinline__ void fma2(ull& c, ull a, ull b) {
    asm("fma.rn.f32x2 %0, %1, %2, %0;" : "+l"(c) : "l"(a), "l"(b));
}
__device__ __forceinline__ float2 unpack2(ull p) {
    float2 v;
    asm("mov.b64 {%0, %1}, %2;" : "=f"(v.x), "=f"(v.y) : "l"(p));
    return v;
}

// ---------------- init: h0 = fp16(concat(emb)); zero cnt/need ----------------
__global__ void k_init(const float* __restrict__ ue, const float* __restrict__ ie,
                       __half* __restrict__ h0,
                       int* __restrict__ cnt, unsigned char* __restrict__ need) {
    int i = blockIdx.x * blockDim.x + threadIdx.x;       // float4 index
    const int total = N_NODES * (LATENT / 4);
    const int usplit = N_USERS * (LATENT / 4);
    if (i < total) {
        float4 v = (i < usplit) ? ((const float4*)ue)[i]
                                : ((const float4*)ie)[i - usplit];
        ((half2*)h0)[i * 2]     = __floats2half2_rn(v.x, v.y);
        ((half2*)h0)[i * 2 + 1] = __floats2half2_rn(v.z, v.w);
    }
    if (i < N_NODES) cnt[i] = 0;
    if (i < N_USERS) need[i] = 0;
}

// ---------------- CSR build: count (4 edges/thread) ----------------
__global__ void k_count(const int* __restrict__ rows, int* __restrict__ cnt) {
    int e4 = blockIdx.x * blockDim.x + threadIdx.x;
    if (e4 < NNZ / 4) {
        int4 r = ((const int4*)rows)[e4];
        atomicAdd(&cnt[r.x], 1);
        atomicAdd(&cnt[r.y], 1);
        atomicAdd(&cnt[r.z], 1);
        atomicAdd(&cnt[r.w], 1);
    }
}

__global__ __launch_bounds__(256) void k_scan_blocks(const int* __restrict__ cnt,
                                                     int* __restrict__ rowstart,
                                                     int* __restrict__ blocksums) {
    __shared__ int wsum[8];
    __shared__ int woff[8];
    int tid  = threadIdx.x;
    int lane = tid & 31;
    int warp = tid >> 5;
    int base = blockIdx.x * SCAN_CHUNK + tid * 4;

    int c0 = 0, c1 = 0, c2 = 0, c3 = 0;
    if (base + 3 < N_NODES) {
        int4 c = *(const int4*)(cnt + base);
        c0 = c.x; c1 = c.y; c2 = c.z; c3 = c.w;
    } else {
        if (base + 0 < N_NODES) c0 = cnt[base + 0];
        if (base + 1 < N_NODES) c1 = cnt[base + 1];
        if (base + 2 < N_NODES) c2 = cnt[base + 2];
        if (base + 3 < N_NODES) c3 = cnt[base + 3];
    }
    int tsum = c0 + c1 + c2 + c3;

    int inc = tsum;
    #pragma unroll
    for (int off = 1; off < 32; off <<= 1) {
        int n = __shfl_up_sync(0xffffffffu, inc, off);
        if (lane >= off) inc += n;
    }
    if (lane == 31) wsum[warp] = inc;
    __syncthreads();
    if (tid == 0) {
        int r = 0;
        #pragma unroll
        for (int i = 0; i < 8; i++) { woff[i] = r; r += wsum[i]; }
        blocksums[blockIdx.x] = r;           // raw chunk sum
    }
    __syncthreads();

    int excl = woff[warp] + (inc - tsum);
    if (base + 0 < N_NODES) rowstart[base + 0] = excl;
    if (base + 1 < N_NODES) rowstart[base + 1] = excl + c0;
    if (base + 2 < N_NODES) rowstart[base + 2] = excl + c0 + c1;
    if (base + 3 < N_NODES) rowstart[base + 3] = excl + c0 + c1 + c2;
}

// add chunk-prefix + init cursor
__global__ __launch_bounds__(256) void k_add_offsets(int* __restrict__ rowstart,
                                                     const int* __restrict__ blocksums,
                                                     int* __restrict__ cursor) {
    __shared__ int s_off;
    int chunk = blockIdx.x >> 2;             // 4 blocks of 256 per 1024-chunk
    if (threadIdx.x < 32) {
        int v = 0;
        for (int j = threadIdx.x; j < chunk; j += 32) v += blocksums[j];
        #pragma unroll
        for (int o = 16; o; o >>= 1) v += __shfl_down_sync(0xffffffffu, v, o);
        if (threadIdx.x == 0) s_off = v;
    }
    __syncthreads();
    int i = blockIdx.x * 256 + threadIdx.x;
    if (i < N_NODES) {
        int r = rowstart[i] + s_off;
        rowstart[i] = r;
        cursor[i]   = r;
    }
}

// ---------------- CSR build: fill (4 edges/thread) ----------------
__global__ void k_fill(const float* __restrict__ vals,
                       const int*   __restrict__ rows,
                       const int*   __restrict__ cols,
                       int* __restrict__ cursor,
                       int2* __restrict__ edge) {
    int e4 = blockIdx.x * blockDim.x + threadIdx.x;
    if (e4 < NNZ / 4) {
        int4   r = ((const int4*)rows)[e4];
        int4   c = ((const int4*)cols)[e4];
        float4 v = ((const float4*)vals)[e4];
        int p;
        p = atomicAdd(&cursor[r.x], 1); edge[p] = make_int2(__float_as_int(v.x), c.x);
        p = atomicAdd(&cursor[r.y], 1); edge[p] = make_int2(__float_as_int(v.y), c.y);
        p = atomicAdd(&cursor[r.z], 1); edge[p] = make_int2(__float_as_int(v.z), c.z);
        p = atomicAdd(&cursor[r.w], 1); edge[p] = make_int2(__float_as_int(v.w), c.w);
    }
}

__global__ void k_setflags(const int* __restrict__ users, unsigned char* __restrict__ need) {
    int i = blockIdx.x * blockDim.x + threadIdx.x;
    if (i < BATCH) need[users[i]] = 1;
}

// ---------------- layer: fp16 segment gather, fp32 accumulate ----------------
// acc is only ever READ for batch users + items, so L1/L2 skip the acc R/M/W
// for non-needed user rows (edst is still written for every row).
// mode 0: acc += s (selective users), write edst        (middle layer)
// mode 1: acc  = emb + s (selective users), write edst  (first layer)
// mode 2: acc += s, no edst, selective row skip          (last layer)
__global__ __launch_bounds__(256) void k_gather(const int2* __restrict__ edge,
                                                const int*  __restrict__ rowstart,
                                                const int*  __restrict__ cnt,
                                                const __half* __restrict__ esrc,
                                                __half*       __restrict__ edst,
                                                float*        __restrict__ acc,
                                                const unsigned char* __restrict__ need,
                                                const float* __restrict__ ue,
                                                const float* __restrict__ ie,
                                                int mode) {
    int g   = blockIdx.x * blockDim.x + threadIdx.x;
    int row = g >> 3;
    int t   = g & 7;
    if (row >= N_NODES) return;
    const bool user_unneeded = (row < N_USERS) && !need[row];
    if (mode == 2 && user_unneeded) return;
    unsigned gmask = 0xFFu << (threadIdx.x & 24);   // own 8-lane group

    const int start = rowstart[row];
    const int deg   = cnt[row];
    float s0 = 0.f, s1 = 0.f, s2 = 0.f, s3 = 0.f;
    float s4 = 0.f, s5 = 0.f, s6 = 0.f, s7 = 0.f;

    const int2* ep = edge + start;
    const __half* srcbase = esrc + t * 8;
    int base = 0;
    const int full = deg & ~7;

    for (; base < full; base += 8) {
        int2 ev = __ldg(&ep[base + t]);
        float v[8]; int c[8];
        #pragma unroll
        for (int k = 0; k < 8; k++) {
            v[k] = __int_as_float(__shfl_sync(gmask, ev.x, k, 8));
            c[k] = __shfl_sync(gmask, ev.y, k, 8);
        }
        uint4 m[8];
        #pragma unroll
        for (int k = 0; k < 8; k++)
            m[k] = __ldg((const uint4*)(srcbase + (size_t)c[k] * LATENT));
        #pragma unroll
        for (int k = 0; k < 8; k++) {
            float2 f0 = __half22float2(*(half2*)&m[k].x);
            float2 f1 = __half22float2(*(half2*)&m[k].y);
            float2 f2 = __half22float2(*(half2*)&m[k].z);
            float2 f3 = __half22float2(*(half2*)&m[k].w);
            s0 += v[k] * f0.x; s1 += v[k] * f0.y;
            s2 += v[k] * f1.x; s3 += v[k] * f1.y;
            s4 += v[k] * f2.x; s5 += v[k] * f2.y;
            s6 += v[k] * f3.x; s7 += v[k] * f3.y;
        }
    }
    if (base < deg) {
        int rem = deg - base;
        int2 ev = (t < rem) ? __ldg(&ep[base + t]) : make_int2(0, 0);
        for (int k = 0; k < rem; k++) {
            float v = __int_as_float(__shfl_sync(gmask, ev.x, k, 8));
            int   c = __shfl_sync(gmask, ev.y, k, 8);
            uint4 m = __ldg((const uint4*)(srcbase + (size_t)c * LATENT));
            float2 f0 = __half22float2(*(half2*)&m.x);
            float2 f1 = __half22float2(*(half2*)&m.y);
            float2 f2 = __half22float2(*(half2*)&m.z);
            float2 f3 = __half22float2(*(half2*)&m.w);
            s0 += v * f0.x; s1 += v * f0.y;
            s2 += v * f1.x; s3 += v * f1.y;
            s4 += v * f2.x; s5 += v * f2.y;
            s6 += v * f3.x; s7 += v * f3.y;
        }
    }

    size_t idx = (size_t)row * LATENT + t * 8;
    if (!user_unneeded) {
        float4 a0, a1;
        if (mode == 1) {
            const float* emb = (row < N_USERS) ? (ue + (size_t)row * LATENT)
                                               : (ie + (size_t)(row - N_USERS) * LATENT);
            a0 = *(const float4*)(emb + t * 8);
            a1 = *(const float4*)(emb + t * 8 + 4);
        } else {
            a0 = *(float4*)(acc + idx);
            a1 = *(float4*)(acc + idx + 4);
        }
        a0.x += s0; a0.y += s1; a0.z += s2; a0.w += s3;
        a1.x += s4; a1.y += s5; a1.z += s6; a1.w += s7;
        *(float4*)(acc + idx)     = a0;
        *(float4*)(acc + idx + 4) = a1;
    }
    if (mode != 2) {
        uint4 o;
        *(half2*)&o.x = __floats2half2_rn(s0, s1);
        *(half2*)&o.y = __floats2half2_rn(s2, s3);
        *(half2*)&o.z = __floats2half2_rn(s4, s5);
        *(half2*)&o.w = __floats2half2_rn(s6, s7);
        *(uint4*)(edst + idx) = o;
    }
}

// ---------------- v_clock: Vc[b][64] ----------------
__global__ void k_vclock(const float* __restrict__ cat_emb,
                         const int*   __restrict__ uh3,
                         const int*   __restrict__ users,
                         const float* __restrict__ thetas,
                         float*       __restrict__ Vc) {
    int b = blockIdx.x;
    int d = threadIdx.x;       // 64 threads
    __shared__ float w[TIME_BINS];
    __shared__ float sinv;
    int u = users[b];
    if (d < TIME_BINS) {
        float cur = thetas[b] * (float)(TIME_BINS / (2.0 * CUDART_PI));
        float diff = fabsf(cur - (float)d);
        float delta = fminf(diff, (float)TIME_BINS - diff);
        w[d] = __expf(-0.5f * delta * delta);
    }
    __syncthreads();
    if (d == 0) {
        float s = 0.f;
        #pragma unroll
        for (int h = 0; h < TIME_BINS; h++) s += w[h];
        sinv = 1.0f / (s + 1e-8f);
    }
    __syncthreads();
    float inv3 = sinv * (1.0f / 3.0f);
    float v = 0.f;
    const int* base = &uh3[u * TIME_BINS * 3];
    #pragma unroll 4
    for (int h = 0; h < TIME_BINS; h++) {
        int c0 = base[h * 3 + 0], c1 = base[h * 3 + 1], c2 = base[h * 3 + 2];
        float e = cat_emb[c0 * 64 + d] + cat_emb[c1 * 64 + d] + cat_emb[c2 * 64 + d];
        v += w[h] * e;
    }
    Vc[b * 64 + d] = v * inv3;
}

// ---------------- clock table: CT[cat][b] = ALPHA * cat_emb[cat] . Vc[b] ----------------
#define CT_CATS 8
__global__ __launch_bounds__(256) void k_ct(const float* __restrict__ cat_emb,
                                            const float* __restrict__ Vc,
                                            float* __restrict__ CT) {
    __shared__ float sc[CT_CATS][64];
    int cat0 = blockIdx.y * CT_CATS;
    for (int i = threadIdx.x; i < CT_CATS * 64; i += 256) {
        int cc = cat0 + i / 64;
        sc[i / 64][i % 64] = (cc < N_CATS) ? cat_emb[cc * 64 + (i % 64)] : 0.f;
    }
    __syncthreads();
    int b = blockIdx.x * 256 + threadIdx.x;
    float acc[CT_CATS];
    #pragma unroll
    for (int c = 0; c < CT_CATS; c++) acc[c] = 0.f;
    #pragma unroll 4
    for (int k = 0; k < 64; k += 4) {
        float4 v = *(const float4*)(Vc + b * 64 + k);
        #pragma unroll
        for (int c = 0; c < CT_CATS; c++)
            acc[c] += v.x * sc[c][k] + v.y * sc[c][k + 1] + v.z * sc[c][k + 2] + v.w * sc[c][k + 3];
    }
    #pragma unroll
    for (int c = 0; c < CT_CATS; c++)
        if (cat0 + c < N_CATS) CT[(cat0 + c) * BATCH + b] = ALPHA * acc[c];
}

// ---------------- GEMM K=64, BK=16 + smem-staged CT epilogue ----------------
#define BM 128
#define BN 128
#define BK 16
#define TM 8
#define TN 8
#define CT_PAD 132   // multiple of 4 -> float4-aligned staging; epilogue reads broadcast
#define SM_AS 0
#define SM_BS 8192
#define SM_CT 16384
#define SM_GEMM_TOTAL (SM_CT + 128 * CT_PAD * 4)

__global__ __launch_bounds__(256, 2) void k_gemm(const float* __restrict__ acc,
                                                 const int*   __restrict__ users,
                                                 const int*   __restrict__ item_cat,
                                                 const float* __restrict__ CT,
                                                 float* __restrict__ C) {
    extern __shared__ __align__(16) char smem_raw[];
    float (*As)[BM] = (float(*)[BM])(smem_raw + SM_AS);
    float (*Bs)[BN] = (float(*)[BN])(smem_raw + SM_BS);
    float* sct = (float*)(smem_raw + SM_CT);

    const int tid  = threadIdx.x;
    const int row0 = blockIdx.y * BM;   // batch offset
    const int col0 = blockIdx.x * BN;   // item offset
    const int ty   = tid / 16;
    const int tx   = tid % 16;

    ull facc[TM][TN / 2];
    #pragma unroll
    for (int i = 0; i < TM; i++)
        #pragma unroll
        for (int j = 0; j < TN / 2; j++) facc[i][j] = 0ull;

    const int lr = tid >> 1;          // 0..127
    const int lq = (tid & 1) * 8;     // 0 or 8 (8-float segment within BK=16)

    const int u = users[row0 + lr];
    const float* aptr = acc + (size_t)u * LATENT;
    const int bcol = col0 + lr;
    const bool bvalid = bcol < M_ITEMS;
    const float* bptr = acc + (size_t)(N_USERS + bcol) * LATENT;

    // prefetch k0 = 0
    float4 pa0 = *(const float4*)(aptr + lq);
    float4 pa1 = *(const float4*)(aptr + lq + 4);
    float4 pb0 = bvalid ? *(const float4*)(bptr + lq)     : make_float4(0.f, 0.f, 0.f, 0.f);
    float4 pb1 = bvalid ? *(const float4*)(bptr + lq + 4) : make_float4(0.f, 0.f, 0.f, 0.f);

    #pragma unroll
    for (int k0 = 0; k0 < LATENT; k0 += BK) {
        As[lq + 0][lr] = pa0.x; As[lq + 1][lr] = pa0.y; As[lq + 2][lr] = pa0.z; As[lq + 3][lr] = pa0.w;
        As[lq + 4][lr] = pa1.x; As[lq + 5][lr] = pa1.y; As[lq + 6][lr] = pa1.z; As[lq + 7][lr] = pa1.w;
        Bs[lq + 0][lr] = pb0.x; Bs[lq + 1][lr] = pb0.y; Bs[lq + 2][lr] = pb0.z; Bs[lq + 3][lr] = pb0.w;
        Bs[lq + 4][lr] = pb1.x; Bs[lq + 5][lr] = pb1.y; Bs[lq + 6][lr] = pb1.z; Bs[lq + 7][lr] = pb1.w;
        __syncthreads();

        if (k0 + BK < LATENT) {
            int kn = k0 + BK + lq;
            pa0 = *(const float4*)(aptr + kn);
            pa1 = *(const float4*)(aptr + kn + 4);
            pb0 = bvalid ? *(const float4*)(bptr + kn)     : make_float4(0.f, 0.f, 0.f, 0.f);
            pb1 = bvalid ? *(const float4*)(bptr + kn + 4) : make_float4(0.f, 0.f, 0.f, 0.f);
        }

        #pragma unroll
        for (int kk = 0; kk < BK; kk++) {
            float4 a0 = *(const float4*)&As[kk][ty * TM];
            float4 a1 = *(const float4*)&As[kk][ty * TM + 4];
            ulonglong2 bp0 = *(const ulonglong2*)&Bs[kk][tx * TN];
            ulonglong2 bp1 = *(const ulonglong2*)&Bs[kk][tx * TN + 4];
            ull ap[TM];
            ap[0] = dup2(a0.x); ap[1] = dup2(a0.y); ap[2] = dup2(a0.z); ap[3] = dup2(a0.w);
            ap[4] = dup2(a1.x); ap[5] = dup2(a1.y); ap[6] = dup2(a1.z); ap[7] = dup2(a1.w);
            #pragma unroll
            for (int i = 0; i < TM; i++) {
                fma2(facc[i][0], ap[i], bp0.x);
                fma2(facc[i][1], ap[i], bp0.y);
                fma2(facc[i][2], ap[i], bp1.x);
                fma2(facc[i][3], ap[i], bp1.y);
            }
        }
        __syncthreads();
    }

    // ---- stage CT into smem: warp w covers columns 16w..16w+15, coalesced rows ----
    {
        const int w    = tid >> 5;
        const int lane = tid & 31;
        #pragma unroll
        for (int cc = 0; cc < 16; cc += 4) {
            int cat4[4];
            #pragma unroll
            for (int q = 0; q < 4; q++) {
                int col = col0 + w * 16 + cc + q;
                cat4[q] = (col < M_ITEMS) ? __ldg(&item_cat[col]) : 0;
            }
            float4 v4[4];
            #pragma unroll
            for (int q = 0; q < 4; q++)
                v4[q] = __ldg((const float4*)(CT + (size_t)cat4[q] * BATCH + row0 + lane * 4));
            #pragma unroll
            for (int q = 0; q < 4; q++)
                *(float4*)(sct + (w * 16 + cc + q) * CT_PAD + lane * 4) = v4[q];
        }
    }
    __syncthreads();

    // ---- epilogue: scale + smem CT + store ----
    const float scale = 0.0625f;     // 0.25 (user layer-mean) * 0.25 (item layer-mean)
    #pragma unroll
    for (int i = 0; i < TM; i++) {
        int r_loc = ty * TM + i;
        int r = row0 + r_loc;            // always < 1024
        float ct[TN];
        #pragma unroll
        for (int j = 0; j < TN; j++)
            ct[j] = sct[(tx * TN + j) * CT_PAD + r_loc];
        #pragma unroll
        for (int j = 0; j < TN / 2; j += 2) {
            int c = col0 + tx * TN + j * 2;
            if (c < M_ITEMS) {
                float2 v0 = unpack2(facc[i][j]);
                float2 v1 = unpack2(facc[i][j + 1]);
                float4 o = make_float4(scale * v0.x + ct[j * 2 + 0],
                                       scale * v0.y + ct[j * 2 + 1],
                                       scale * v1.x + ct[j * 2 + 2],
                                       scale * v1.y + ct[j * 2 + 3]);
                *(float4*)(C + (size_t)r * M_ITEMS + c) = o;
            }
        }
    }
}

// ---------------- launch ----------------
extern "C" void kernel_launch(void* const* d_in, const int* in_sizes, int n_in,
                              void* d_out, int out_size) {
    const float* user_emb  = (const float*)d_in[0];
    const float* item_emb  = (const float*)d_in[1];
    const float* cat_emb   = (const float*)d_in[2];
    const float* graph_vals= (const float*)d_in[3];
    const int*   graph_rows= (const int*)  d_in[4];
    const int*   graph_cols= (const int*)  d_in[5];
    const int*   uh3       = (const int*)  d_in[6];
    const int*   item_cat  = (const int*)  d_in[7];
    const int*   users     = (const int*)  d_in[8];
    const float* thetas    = (const float*)d_in[9];
    float* out = (float*)d_out;

    __half *d_h0, *d_h1;
    float *d_acc, *d_Vc, *d_CT;
    int2* d_edge; int *d_cnt, *d_rowstart, *d_cursor, *d_blocksums;
    unsigned char* d_need;
    cudaGetSymbolAddress((void**)&d_h0,       g_h0);
    cudaGetSymbolAddress((void**)&d_h1,       g_h1);
    cudaGetSymbolAddress((void**)&d_acc,      g_acc);
    cudaGetSymbolAddress((void**)&d_Vc,       g_Vc);
    cudaGetSymbolAddress((void**)&d_CT,       g_CT);
    cudaGetSymbolAddress((void**)&d_edge,     g_edge);
    cudaGetSymbolAddress((void**)&d_cnt,      g_cnt);
    cudaGetSymbolAddress((void**)&d_rowstart, g_rowstart);
    cudaGetSymbolAddress((void**)&d_cursor,   g_cursor);
    cudaGetSymbolAddress((void**)&d_blocksums,g_blocksums);
    cudaGetSymbolAddress((void**)&d_need,     g_need);

    cudaFuncSetAttribute(k_gemm, cudaFuncAttributeMaxDynamicSharedMemorySize, SM_GEMM_TOTAL);

    // 1: init (h0 + zero cnt/need)
    {
        int total = N_NODES * (LATENT / 4);
        k_init<<<(total + 255) / 256, 256>>>(user_emb, item_emb, d_h0, d_cnt, d_need);
    }
    // 2-5: CSR build (compact, L2-resident edges); flags before gathers
    k_count<<<(NNZ / 4 + 255) / 256, 256>>>(graph_rows, d_cnt);
    k_scan_blocks<<<NBLK, 256>>>(d_cnt, d_rowstart, d_blocksums);
    k_add_offsets<<<NBLK * 4, 256>>>(d_rowstart, d_blocksums, d_cursor);
    k_fill<<<(NNZ / 4 + 255) / 256, 256>>>(graph_vals, graph_rows, graph_cols, d_cursor, d_edge);
    k_setflags<<<(BATCH + 255) / 256, 256>>>(users, d_need);

    // 6-8: LightGCN layers (acc maintained selectively for users)
    {
        int th = N_NODES * 8;
        int blocks = (th + 255) / 256;
        k_gather<<<blocks, 256>>>(d_edge, d_rowstart, d_cnt, d_h0, d_h1, d_acc, d_need,
                                  user_emb, item_emb, 1);   // L1
        k_gather<<<blocks, 256>>>(d_edge, d_rowstart, d_cnt, d_h1, d_h0, d_acc, d_need,
                                  user_emb, item_emb, 0);   // L2
        k_gather<<<blocks, 256>>>(d_edge, d_rowstart, d_cnt, d_h0, d_h1, d_acc, d_need,
                                  user_emb, item_emb, 2);   // L3: selective rows
    }

    // 9-10: clock path
    k_vclock<<<BATCH, 64>>>(cat_emb, uh3, users, thetas, d_Vc);
    {
        dim3 grid(BATCH / 256, (N_CATS + CT_CATS - 1) / CT_CATS);
        k_ct<<<grid, 256>>>(cat_emb, d_Vc, d_CT);
    }

    // 11: fused GEMM (K=64) + staged-CT epilogue
    {
        dim3 grid(M_PAD / BN, BATCH / BM);
        k_gemm<<<grid, 256, SM_GEMM_TOTAL>>>(d_acc, users, item_cat, d_CT, out);
    }
}